// round 5
// baseline (speedup 1.0000x reference)
#include <cuda_runtime.h>

// Causal FlashAttention fp32, SIMT f32x2 FMA, 8x8 register blocking (sm_103a).
// 128x128 tiles, K/V time-share one smem buffer. Online softmax in registers.

#define BR 128
#define BC 128
#define HD 128
#define PS_STRIDE 132   // 128 + 4 pad
#define NTHREADS 256
#define SCALE 0.08838834764831845f  // 1/sqrt(128)

typedef unsigned long long ull;

struct SmemLayout {
    float Qs[HD][BR];        // Q transposed (d-major), pre-scaled   64 KB
    float KV[HD * BC];       // K (d-major) OR V (row-major)         64 KB
    float Ps[BR][PS_STRIDE]; // probabilities                        66 KB
};

__device__ __forceinline__ ull dup2(float x) {
    ull r; unsigned u = __float_as_uint(x);
    asm("mov.b64 %0, {%1, %1};" : "=l"(r) : "r"(u));
    return r;
}
__device__ __forceinline__ void unpack2(ull p, float& lo, float& hi) {
    unsigned a, b;
    asm("mov.b64 {%0, %1}, %2;" : "=r"(a), "=r"(b) : "l"(p));
    lo = __uint_as_float(a); hi = __uint_as_float(b);
}
__device__ __forceinline__ ull ffma2(ull a, ull b, ull c) {
    ull d;
    asm("fma.rn.f32x2 %0, %1, %2, %3;" : "=l"(d) : "l"(a), "l"(b), "l"(c));
    return d;
}
__device__ __forceinline__ ull fmul2(ull a, ull b) {
    ull d;
    asm("mul.rn.f32x2 %0, %1, %2;" : "=l"(d) : "l"(a), "l"(b));
    return d;
}

__global__ __launch_bounds__(NTHREADS, 1)
void flash_fwd_kernel(const float* __restrict__ gq,
                      const float* __restrict__ gk,
                      const float* __restrict__ gv,
                      float* __restrict__ gout,
                      int seqlen)
{
    extern __shared__ char raw[];
    SmemLayout* sm = reinterpret_cast<SmemLayout*>(raw);

    const int tid = threadIdx.x;
    const int tx = tid & 15;        // 16 col groups: cols tx*8 .. tx*8+7
    const int ty = tid >> 4;        // 16 row groups: rows ty*8 .. ty*8+7
    const int bh = blockIdx.y;
    const int qtile = gridDim.x - 1 - blockIdx.x;   // heavy tiles first
    const int qbase = qtile * BR;
    const size_t bh_off = (size_t)bh * seqlen * HD;

    // ---- Load Q tile transposed (d-major), fold scale ----
    {
        int r = tid & 127;          // consecutive lanes -> consecutive rows: STS conflict-free
        int cg = tid >> 7;          // 2 chunk groups
        const float* qp = gq + bh_off + (size_t)(qbase + r) * HD;
        #pragma unroll
        for (int jj = 0; jj < 16; ++jj) {
            int c = cg + jj * 2;    // float4 chunk 0..31
            float4 t = *(const float4*)(qp + c * 4);
            sm->Qs[c * 4 + 0][r] = t.x * SCALE;
            sm->Qs[c * 4 + 1][r] = t.y * SCALE;
            sm->Qs[c * 4 + 2][r] = t.z * SCALE;
            sm->Qs[c * 4 + 3][r] = t.w * SCALE;
        }
    }

    // Per-thread state: 8 rows, 8 cols of O
    float m_r[8], l_r[8];
    ull acco[8][4];   // row r, col-pairs {8tx+0,1}{2,3}{4,5}{6,7}
    #pragma unroll
    for (int r = 0; r < 8; ++r) {
        m_r[r] = -1e30f; l_r[r] = 0.0f;
        #pragma unroll
        for (int c = 0; c < 4; ++c) acco[r][c] = 0ull;
    }

    for (int j = 0; j <= qtile; ++j) {
        const int kbase = j * BC;
        __syncthreads();   // prev-iter readers of KV(V)/Ps done before K overwrite

        // ---- K tile transposed (d-major) into KV ----
        float (*Ks)[BC] = reinterpret_cast<float (*)[BC]>(sm->KV);
        {
            int r = tid & 127;
            int cg = tid >> 7;
            const float* kp = gk + bh_off + (size_t)(kbase + r) * HD;
            #pragma unroll
            for (int jj = 0; jj < 16; ++jj) {
                int c = cg + jj * 2;
                float4 t = *(const float4*)(kp + c * 4);
                Ks[c * 4 + 0][r] = t.x;
                Ks[c * 4 + 1][r] = t.y;
                Ks[c * 4 + 2][r] = t.z;
                Ks[c * 4 + 3][r] = t.w;
            }
        }
        __syncthreads();

        // ---- S = Q @ K^T : 8x8 per thread, rows paired in f32x2 ----
        ull accs[4][8];   // row-pair rp = rows (2rp, 2rp+1), 8 cols
        #pragma unroll
        for (int rp = 0; rp < 4; ++rp)
            #pragma unroll
            for (int c = 0; c < 8; ++c) accs[rp][c] = 0ull;

        {
            const float* qcol = &sm->Qs[0][ty * 8];
            const float* kcol = &Ks[0][tx * 8];
            #pragma unroll 2
            for (int kk = 0; kk < HD; ++kk) {
                ulonglong2 a01 = *(const ulonglong2*)(qcol + kk * BR);     // rows 0-3
                ulonglong2 a23 = *(const ulonglong2*)(qcol + kk * BR + 4); // rows 4-7
                float4 b0 = *(const float4*)(kcol + kk * BC);
                float4 b1 = *(const float4*)(kcol + kk * BC + 4);
                ull bd[8];
                bd[0] = dup2(b0.x); bd[1] = dup2(b0.y);
                bd[2] = dup2(b0.z); bd[3] = dup2(b0.w);
                bd[4] = dup2(b1.x); bd[5] = dup2(b1.y);
                bd[6] = dup2(b1.z); bd[7] = dup2(b1.w);
                #pragma unroll
                for (int c = 0; c < 8; ++c) {
                    accs[0][c] = ffma2(a01.x, bd[c], accs[0][c]);
                    accs[1][c] = ffma2(a01.y, bd[c], accs[1][c]);
                    accs[2][c] = ffma2(a23.x, bd[c], accs[2][c]);
                    accs[3][c] = ffma2(a23.y, bd[c], accs[3][c]);
                }
            }
        }

        // ---- online softmax, row-pair at a time (caps live registers) ----
        const bool diag = (j == qtile);
        #pragma unroll
        for (int rp = 0; rp < 4; ++rp) {
            float v[2][8];
            #pragma unroll
            for (int c = 0; c < 8; ++c) unpack2(accs[rp][c], v[0][c], v[1][c]);

            #pragma unroll
            for (int h = 0; h < 2; ++h) {
                const int lr = rp * 2 + h;          // 0..7 local row in thread
                const int lrow = ty * 8 + lr;       // row within tile
                if (diag) {
                    #pragma unroll
                    for (int c = 0; c < 8; ++c)
                        if (tx * 8 + c > lrow) v[h][c] = -1e30f;
                }
                float mx = v[h][0];
                #pragma unroll
                for (int c = 1; c < 8; ++c) mx = fmaxf(mx, v[h][c]);
                #pragma unroll
                for (int off = 8; off >= 1; off >>= 1)
                    mx = fmaxf(mx, __shfl_xor_sync(0xffffffffu, mx, off));

                float mn = fmaxf(m_r[lr], mx);
                float fac = __expf(m_r[lr] - mn);
                m_r[lr] = mn;

                float p[8], rs = 0.0f;
                #pragma unroll
                for (int c = 0; c < 8; ++c) { p[c] = __expf(v[h][c] - mn); rs += p[c]; }
                #pragma unroll
                for (int off = 8; off >= 1; off >>= 1)
                    rs += __shfl_xor_sync(0xffffffffu, rs, off);
                l_r[lr] = l_r[lr] * fac + rs;

                *(float4*)&sm->Ps[lrow][tx * 8]     = make_float4(p[0], p[1], p[2], p[3]);
                *(float4*)&sm->Ps[lrow][tx * 8 + 4] = make_float4(p[4], p[5], p[6], p[7]);

                ull f2 = dup2(fac);
                #pragma unroll
                for (int cp = 0; cp < 4; ++cp) acco[lr][cp] = fmul2(acco[lr][cp], f2);
            }
        }
        __syncthreads();   // S-GEMM reads of KV(K) done; P visible

        // ---- V tile (row-major) into KV ----
        float (*Vs)[HD] = reinterpret_cast<float (*)[HD]>(sm->KV);
        {
            const float* vp = gv + bh_off + (size_t)kbase * HD;
            #pragma unroll
            for (int jj = 0; jj < 16; ++jj) {
                int idx = tid + jj * NTHREADS;      // float4 unit index 0..4095
                int rr = idx >> 5, cc = idx & 31;
                *(float4*)&Vs[rr][cc * 4] = *(const float4*)(vp + rr * HD + cc * 4);
            }
        }
        __syncthreads();

        // ---- O += P @ V : cols paired in f32x2 ----
        {
            const float* prow = &sm->Ps[ty * 8][0];
            #pragma unroll 2
            for (int kv = 0; kv < BC; ++kv) {
                float a[8];
                #pragma unroll
                for (int r = 0; r < 8; ++r) a[r] = prow[r * PS_STRIDE + kv];
                ulonglong2 b01 = *(const ulonglong2*)&Vs[kv][tx * 8];
                ulonglong2 b23 = *(const ulonglong2*)&Vs[kv][tx * 8 + 4];
                #pragma unroll
                for (int r = 0; r < 8; ++r) {
                    ull ad = dup2(a[r]);
                    acco[r][0] = ffma2(ad, b01.x, acco[r][0]);
                    acco[r][1] = ffma2(ad, b01.y, acco[r][1]);
                    acco[r][2] = ffma2(ad, b23.x, acco[r][2]);
                    acco[r][3] = ffma2(ad, b23.y, acco[r][3]);
                }
            }
        }
    }

    // ---- epilogue: O /= l, write out (contiguous 8 cols per thread) ----
    #pragma unroll
    for (int r = 0; r < 8; ++r) {
        float inv = 1.0f / l_r[r];
        float o[8];
        unpack2(acco[r][0], o[0], o[1]);
        unpack2(acco[r][1], o[2], o[3]);
        unpack2(acco[r][2], o[4], o[5]);
        unpack2(acco[r][3], o[6], o[7]);
        float* orow = gout + bh_off + (size_t)(qbase + ty * 8 + r) * HD + tx * 8;
        *(float4*)(orow)     = make_float4(o[0]*inv, o[1]*inv, o[2]*inv, o[3]*inv);
        *(float4*)(orow + 4) = make_float4(o[4]*inv, o[5]*inv, o[6]*inv, o[7]*inv);
    }
}

extern "C" void kernel_launch(void* const* d_in, const int* in_sizes, int n_in,
                              void* d_out, int out_size)
{
    const float* q = (const float*)d_in[0];
    const float* k = (const float*)d_in[1];
    const float* v = (const float*)d_in[2];
    float* out = (float*)d_out;

    const int seqlen = 2048;
    const int nbh = in_sizes[0] / (seqlen * HD);   // B*H = 32

    size_t smem = sizeof(SmemLayout);
    cudaFuncSetAttribute(flash_fwd_kernel,
                         cudaFuncAttributeMaxDynamicSharedMemorySize, (int)smem);

    dim3 grid(seqlen / BR, nbh);
    flash_fwd_kernel<<<grid, NTHREADS, smem>>>(q, k, v, out, seqlen);
}